// round 10
// baseline (speedup 1.0000x reference)
#include <cuda_runtime.h>
#include <cuda_bf16.h>
#include <math.h>
#include <stdint.h>

#define BATCH 4096
#define DIM   1024
#define LN_EPS 1e-5f

// ---------------- GEMM tiling ----------------
#define BM 128
#define BN 256
#define BK 64
#define NSTG 2
#define ROW_HALFS 72                    // 64 data + 8 pad halves (144 B row stride)
#define A_BYTES (BM * ROW_HALFS * 2)    // 18432
#define B_BYTES (BN * ROW_HALFS * 2)    // 36864
#define STG_BYTES (A_BYTES + B_BYTES)   // 55296
#define SMEM_TOTAL (NSTG * STG_BYTES)   // 110592

// ---------------- scratch (static device globals) ----------------
__device__ __align__(256) __nv_bfloat16 g_xhi [(size_t)BATCH * DIM];
__device__ __align__(256) __nv_bfloat16 g_wqhi[(size_t)DIM * DIM];
__device__ __align__(256) __nv_bfloat16 g_wkhi[(size_t)DIM * DIM];
__device__ __align__(256) __nv_bfloat16 g_wvhi[(size_t)DIM * DIM];
__device__ __align__(256) __nv_bfloat16 g_fwhi[(size_t)DIM * DIM];
__device__ __align__(256) __nv_bfloat16 g_qhi [(size_t)BATCH * DIM];
__device__ __align__(256) __nv_bfloat16 g_khi [(size_t)BATCH * DIM];
__device__ __align__(256) __nv_bfloat16 g_vthi[(size_t)DIM * BATCH];    // V^T [DIM, BATCH]
__device__ __align__(256) __nv_bfloat16 g_phi [(size_t)BATCH * BATCH];  // exp-probs bf16 (unnormalized)
__device__ __align__(256) float         g_psum[(size_t)16 * BATCH];     // per-colblock row partial sums
__device__ __align__(256) float         g_rsum[(size_t)BATCH];          // reciprocal row sums
__device__ __align__(256) __nv_bfloat16 g_avhi[(size_t)BATCH * DIM];
__device__ __align__(256) float         g_h   [(size_t)BATCH * DIM];

// ---------------- PTX helpers ----------------
__device__ __forceinline__ uint32_t smem_u32(const void* p) {
    uint32_t a;
    asm("{ .reg .u64 t; cvta.to.shared.u64 t, %1; cvt.u32.u64 %0, t; }" : "=r"(a) : "l"(p));
    return a;
}

#define CP_ASYNC16(dst, src) \
    asm volatile("cp.async.cg.shared.global [%0], [%1], 16;" :: "r"(dst), "l"(src) : "memory")
#define CP_COMMIT() asm volatile("cp.async.commit_group;" ::: "memory")
#define CP_WAIT()   asm volatile("cp.async.wait_group %0;" :: "n"(NSTG - 2) : "memory")
#define CP_WAIT0()  asm volatile("cp.async.wait_group 0;" ::: "memory")

__device__ __forceinline__ void ldm4(uint32_t& r0, uint32_t& r1, uint32_t& r2, uint32_t& r3,
                                     uint32_t addr) {
    asm volatile("ldmatrix.sync.aligned.m8n8.x4.shared.b16 {%0,%1,%2,%3}, [%4];"
                 : "=r"(r0), "=r"(r1), "=r"(r2), "=r"(r3) : "r"(addr));
}

__device__ __forceinline__ void mma16816(float& c0, float& c1, float& c2, float& c3,
                                         uint32_t a0, uint32_t a1, uint32_t a2, uint32_t a3,
                                         uint32_t b0, uint32_t b1) {
    asm volatile("mma.sync.aligned.m16n8k16.row.col.f32.bf16.bf16.f32 "
                 "{%0,%1,%2,%3}, {%4,%5,%6,%7}, {%8,%9}, {%0,%1,%2,%3};"
                 : "+f"(c0), "+f"(c1), "+f"(c2), "+f"(c3)
                 : "r"(a0), "r"(a1), "r"(a2), "r"(a3), "r"(b0), "r"(b1));
}

// stage loader: A tile 128x64 bf16 + B tile 256x64 bf16, padded rows (144B stride)
__device__ __forceinline__ void load_stage(
    uint32_t sbase, int tid,
    const __nv_bfloat16* __restrict__ A, const __nv_bfloat16* __restrict__ B, int K)
{
    #pragma unroll
    for (int i = 0; i < 12; i++) {
        int c   = tid + i * 256;          // 0..3071 chunk id (16B chunks)
        int row, base;
        if (c < 1024) { row = c >> 3; base = 0; }
        else          { row = (c - 1024) >> 3; base = A_BYTES; }
        int col = c & 7;                  // 0..7
        const __nv_bfloat16* src = (c < 1024 ? A : B) + (size_t)row * K + col * 8;
        uint32_t dst = sbase + base + row * (ROW_HALFS * 2) + col * 16;
        CP_ASYNC16(dst, src);
    }
}

// ---------------- HMMA GEMM (128x256 CTA tile, 64x64 warp tiles) ------------
// C[M,N] = A[M,K] x B[N,K]^T  (NT)
// MODE 3: Cf = acc + bias[col] + resid          MODE 4: Chi bf16 plain
// MODE 5: Chi bf16 transposed (ld = Mtot)
// MODE 6: Chi = bf16(exp(alpha*acc)); Cf = per-CTA row partial sums (psum layout [gridX][Mtot])
// MODE 7: Chi = bf16(acc * bias[row])           (bias = reciprocal row sums)
template<int MODE>
__global__ __launch_bounds__(256) void gemm_mma(
    const __nv_bfloat16* __restrict__ Ahi,
    const __nv_bfloat16* __restrict__ Bhi,
    int K, int N, int Mtot, float alpha,
    float* __restrict__ Cf, __nv_bfloat16* __restrict__ Chi,
    const float* __restrict__ bias, const float* __restrict__ resid)
{
    extern __shared__ __align__(16) char smem_raw[];
    const uint32_t sb = smem_u32(smem_raw);

    const int tid = threadIdx.x;
    const int wid = tid >> 5;
    const int lid = tid & 31;
    const int warp_m = wid >> 2;          // 0..1  -> 64-row block
    const int warp_n = wid & 3;           // 0..3  -> 64-col block

    const int T = K / BK;
    const size_t arow = (size_t)blockIdx.y * BM * K;
    const size_t brow = (size_t)blockIdx.x * BN * K;

    float acc[4][8][4];
    #pragma unroll
    for (int i = 0; i < 4; i++)
        #pragma unroll
        for (int j = 0; j < 8; j++)
            #pragma unroll
            for (int e = 0; e < 4; e++) acc[i][j][e] = 0.f;

    const int a_r  = lid & 15;
    const int a_k8 = (lid >> 4) & 1;
    const int b_r  = lid & 7;
    const int b_t  = (lid >> 4) & 1;
    const int b_k8 = (lid >> 3) & 1;

    // ks-invariant fragment address bases
    const uint32_t aFr = (warp_m * 64 + a_r) * (ROW_HALFS * 2) + a_k8 * 16;
    const uint32_t bFr = (warp_n * 64 + b_t * 8 + b_r) * (ROW_HALFS * 2) + b_k8 * 16;

    // prologue: fill NSTG-1 stages
    #pragma unroll
    for (int u = 0; u < NSTG - 1; u++) {
        load_stage(sb + u * STG_BYTES, tid, Ahi + arow + u * BK, Bhi + brow + u * BK, K);
        CP_COMMIT();
    }

    for (int t = 0; t < T; t++) {
        CP_WAIT();
        __syncthreads();

        const int u = t + NSTG - 1;
        if (u < T) {
            int su = u & (NSTG - 1);
            load_stage(sb + su * STG_BYTES, tid, Ahi + arow + u * BK, Bhi + brow + u * BK, K);
        }
        CP_COMMIT();

        const uint32_t aB = sb + (t & (NSTG - 1)) * STG_BYTES;
        const uint32_t bB = aB + A_BYTES;
        #pragma unroll
        for (int ks = 0; ks < 4; ks++) {
            const uint32_t ko = ks * 32;   // 16 halfs = 32 bytes
            uint32_t a[4][4];
            #pragma unroll
            for (int mi = 0; mi < 4; mi++)
                ldm4(a[mi][0], a[mi][1], a[mi][2], a[mi][3],
                     aB + aFr + mi * 16 * (ROW_HALFS * 2) + ko);
            uint32_t b[8][2];
            #pragma unroll
            for (int j = 0; j < 4; j++)
                ldm4(b[2 * j][0], b[2 * j][1], b[2 * j + 1][0], b[2 * j + 1][1],
                     bB + bFr + j * 16 * (ROW_HALFS * 2) + ko);
            #pragma unroll
            for (int mi = 0; mi < 4; mi++)
                #pragma unroll
                for (int ni = 0; ni < 8; ni++)
                    mma16816(acc[mi][ni][0], acc[mi][ni][1], acc[mi][ni][2], acc[mi][ni][3],
                             a[mi][0], a[mi][1], a[mi][2], a[mi][3],
                             b[ni][0], b[ni][1]);
        }
    }

    // ---------------- epilogue ----------------
    const int qr = lid >> 2;              // 0..7
    const int qc = (lid & 3) * 2;         // 0,2,4,6

    if (MODE == 6) {
        // probs = exp(alpha*acc) -> bf16; per-CTA row sums -> Cf (psum[gridX][Mtot])
        CP_WAIT0();
        __syncthreads();
        float* ps = reinterpret_cast<float*>(smem_raw);   // [4][128]
        #pragma unroll
        for (int mi = 0; mi < 4; mi++) {
            #pragma unroll
            for (int half = 0; half < 2; half++) {
                const int rl = warp_m * 64 + mi * 16 + qr + half * 8;
                const int r  = blockIdx.y * BM + rl;
                float rp = 0.f;
                #pragma unroll
                for (int ni = 0; ni < 8; ni++) {
                    const int c = blockIdx.x * BN + warp_n * 64 + ni * 8 + qc;
                    float p0 = __expf(acc[mi][ni][half * 2 + 0] * alpha);
                    float p1 = __expf(acc[mi][ni][half * 2 + 1] * alpha);
                    *reinterpret_cast<__nv_bfloat162*>(Chi + (size_t)r * N + c) =
                        __halves2bfloat162(__float2bfloat16_rn(p0), __float2bfloat16_rn(p1));
                    rp += p0 + p1;
                }
                rp += __shfl_xor_sync(0xffffffffu, rp, 1);
                rp += __shfl_xor_sync(0xffffffffu, rp, 2);
                if ((lid & 3) == 0) ps[warp_n * 128 + rl] = rp;
            }
        }
        __syncthreads();
        if (tid < 128) {
            float s = ps[tid] + ps[128 + tid] + ps[256 + tid] + ps[384 + tid];
            Cf[(size_t)blockIdx.x * Mtot + blockIdx.y * BM + tid] = s;
        }
        return;
    }

    #pragma unroll
    for (int mi = 0; mi < 4; mi++) {
        #pragma unroll
        for (int half = 0; half < 2; half++) {
            const int r = blockIdx.y * BM + warp_m * 64 + mi * 16 + qr + half * 8;
            const float rs = (MODE == 7) ? bias[r] : 0.f;
            #pragma unroll
            for (int ni = 0; ni < 8; ni++) {
                const int c = blockIdx.x * BN + warp_n * 64 + ni * 8 + qc;
                float f0 = acc[mi][ni][half * 2 + 0];
                float f1 = acc[mi][ni][half * 2 + 1];
                if (MODE == 3) {
                    const float2 b2 = *reinterpret_cast<const float2*>(bias + c);
                    const float2 x2 = *reinterpret_cast<const float2*>(resid + (size_t)r * N + c);
                    float2 o = {f0 + b2.x + x2.x, f1 + b2.y + x2.y};
                    *reinterpret_cast<float2*>(Cf + (size_t)r * N + c) = o;
                } else if (MODE == 4) {
                    *reinterpret_cast<__nv_bfloat162*>(Chi + (size_t)r * N + c) =
                        __halves2bfloat162(__float2bfloat16_rn(f0), __float2bfloat16_rn(f1));
                } else if (MODE == 7) {
                    *reinterpret_cast<__nv_bfloat162*>(Chi + (size_t)r * N + c) =
                        __halves2bfloat162(__float2bfloat16_rn(f0 * rs),
                                           __float2bfloat16_rn(f1 * rs));
                } else { // MODE 5: plain bf16 transposed write (produces V^T)
                    Chi[(size_t)(c + 0) * Mtot + r] = __float2bfloat16_rn(f0);
                    Chi[(size_t)(c + 1) * Mtot + r] = __float2bfloat16_rn(f1);
                }
            }
        }
    }
}

// ---------------- reciprocal row sums: rsum[r] = 1 / sum_b psum[b][r] ------
__global__ __launch_bounds__(256) void rowsum_recip(
    const float* __restrict__ ps, float* __restrict__ rs)
{
    int r = blockIdx.x * 256 + threadIdx.x;
    float s = 0.f;
    #pragma unroll
    for (int b = 0; b < 16; b++) s += ps[(size_t)b * BATCH + r];
    rs[r] = 1.f / s;
}

// ---------------- fp32 -> bf16 convert (single tensor) ----------------
__global__ __launch_bounds__(256) void cvt_bf16(
    const float* __restrict__ src, __nv_bfloat16* __restrict__ dst, int n4)
{
    int i = blockIdx.x * 256 + threadIdx.x;
    if (i >= n4) return;
    float4 v = reinterpret_cast<const float4*>(src)[i];
    reinterpret_cast<__nv_bfloat162*>(dst)[i * 2 + 0] =
        __halves2bfloat162(__float2bfloat16_rn(v.x), __float2bfloat16_rn(v.y));
    reinterpret_cast<__nv_bfloat162*>(dst)[i * 2 + 1] =
        __halves2bfloat162(__float2bfloat16_rn(v.z), __float2bfloat16_rn(v.w));
}

// ---------------- fp32 -> bf16 convert (4 weight tensors, one launch) -------
__global__ __launch_bounds__(256) void cvt_bf16_w4(
    const float* __restrict__ s0, const float* __restrict__ s1,
    const float* __restrict__ s2, const float* __restrict__ s3,
    __nv_bfloat16* __restrict__ d0, __nv_bfloat16* __restrict__ d1,
    __nv_bfloat16* __restrict__ d2, __nv_bfloat16* __restrict__ d3, int n4)
{
    const float* src = blockIdx.y == 0 ? s0 : blockIdx.y == 1 ? s1 : blockIdx.y == 2 ? s2 : s3;
    __nv_bfloat16* dst = blockIdx.y == 0 ? d0 : blockIdx.y == 1 ? d1 : blockIdx.y == 2 ? d2 : d3;
    int i = blockIdx.x * 256 + threadIdx.x;
    if (i >= n4) return;
    float4 v = reinterpret_cast<const float4*>(src)[i];
    reinterpret_cast<__nv_bfloat162*>(dst)[i * 2 + 0] =
        __halves2bfloat162(__float2bfloat16_rn(v.x), __float2bfloat16_rn(v.y));
    reinterpret_cast<__nv_bfloat162*>(dst)[i * 2 + 1] =
        __halves2bfloat162(__float2bfloat16_rn(v.z), __float2bfloat16_rn(v.w));
}

// ---------------- layernorm ----------------
__global__ __launch_bounds__(256) void layernorm_rows(
    const float* __restrict__ H, const float* __restrict__ gamma,
    const float* __restrict__ beta, float* __restrict__ out)
{
    __shared__ float redS[8], redQ[8];
    const int tid = threadIdx.x;
    const float* p = H + (size_t)blockIdx.x * DIM;

    float4 v = *reinterpret_cast<const float4*>(p + tid * 4);
    float s  = v.x + v.y + v.z + v.w;
    float ss = v.x * v.x + v.y * v.y + v.z * v.z + v.w * v.w;
    #pragma unroll
    for (int o = 16; o; o >>= 1) {
        s  += __shfl_xor_sync(0xffffffffu, s, o);
        ss += __shfl_xor_sync(0xffffffffu, ss, o);
    }
    if ((tid & 31) == 0) { redS[tid >> 5] = s; redQ[tid >> 5] = ss; }
    __syncthreads();
    s = 0.f; ss = 0.f;
    #pragma unroll
    for (int i = 0; i < 8; i++) { s += redS[i]; ss += redQ[i]; }

    const float mu  = s * (1.f / DIM);
    const float var = ss * (1.f / DIM) - mu * mu;
    const float rs  = rsqrtf(var + LN_EPS);

    float4 g = *reinterpret_cast<const float4*>(gamma + tid * 4);
    float4 b = *reinterpret_cast<const float4*>(beta  + tid * 4);
    float4 o;
    o.x = (v.x - mu) * rs * g.x + b.x;
    o.y = (v.y - mu) * rs * g.y + b.y;
    o.z = (v.z - mu) * rs * g.z + b.z;
    o.w = (v.w - mu) * rs * g.w + b.w;
    *reinterpret_cast<float4*>(out + (size_t)blockIdx.x * DIM + tid * 4) = o;
}

// ---------------- launch ----------------
extern "C" void kernel_launch(void* const* d_in, const int* in_sizes, int n_in,
                              void* d_out, int out_size)
{
    const float* x     = (const float*)d_in[0];
    const float* Wq    = (const float*)d_in[1];
    const float* Wk    = (const float*)d_in[2];
    const float* Wv    = (const float*)d_in[3];
    const float* fcw   = (const float*)d_in[4];
    const float* fcb   = (const float*)d_in[5];
    const float* gamma = (const float*)d_in[6];
    const float* beta  = (const float*)d_in[7];
    float* out = (float*)d_out;

    __nv_bfloat16 *xhi, *wqhi, *wkhi, *wvhi, *fwhi;
    __nv_bfloat16 *qhi, *khi, *vthi, *phi, *avhi;
    float *psum, *rsum, *h;
    cudaGetSymbolAddress((void**)&xhi,  g_xhi);
    cudaGetSymbolAddress((void**)&wqhi, g_wqhi);
    cudaGetSymbolAddress((void**)&wkhi, g_wkhi);
    cudaGetSymbolAddress((void**)&wvhi, g_wvhi);
    cudaGetSymbolAddress((void**)&fwhi, g_fwhi);
    cudaGetSymbolAddress((void**)&qhi,  g_qhi);
    cudaGetSymbolAddress((void**)&khi,  g_khi);
    cudaGetSymbolAddress((void**)&vthi, g_vthi);
    cudaGetSymbolAddress((void**)&phi,  g_phi);
    cudaGetSymbolAddress((void**)&psum, g_psum);
    cudaGetSymbolAddress((void**)&rsum, g_rsum);
    cudaGetSymbolAddress((void**)&avhi, g_avhi);
    cudaGetSymbolAddress((void**)&h,    g_h);

    cudaFuncSetAttribute(gemm_mma<4>, cudaFuncAttributeMaxDynamicSharedMemorySize, SMEM_TOTAL);
    cudaFuncSetAttribute(gemm_mma<5>, cudaFuncAttributeMaxDynamicSharedMemorySize, SMEM_TOTAL);
    cudaFuncSetAttribute(gemm_mma<6>, cudaFuncAttributeMaxDynamicSharedMemorySize, SMEM_TOTAL);
    cudaFuncSetAttribute(gemm_mma<7>, cudaFuncAttributeMaxDynamicSharedMemorySize, SMEM_TOTAL);
    cudaFuncSetAttribute(gemm_mma<3>, cudaFuncAttributeMaxDynamicSharedMemorySize, SMEM_TOTAL);

    // convert inputs to bf16
    const int nX = BATCH * DIM / 4, nW = DIM * DIM / 4;
    cvt_bf16<<<(nX + 255) / 256, 256>>>(x, xhi, nX);
    cvt_bf16_w4<<<dim3((nW + 255) / 256, 4), 256>>>(Wq, Wk, Wv, fcw,
                                                    wqhi, wkhi, wvhi, fwhi, nW);

    const dim3 blk(256);
    const dim3 gP(DIM / BN,   BATCH / BM);   // 4 x 32  (128 CTAs, single wave)
    const dim3 gS(BATCH / BN, BATCH / BM);   // 16 x 32

    // q = x@Wq^T, k = x@Wk^T (bf16 out); v = x@Wv^T (bf16, transposed out)
    gemm_mma<4><<<gP, blk, SMEM_TOTAL>>>(xhi, wqhi, DIM, DIM, BATCH, 1.f,
                                         nullptr, qhi, nullptr, nullptr);
    gemm_mma<4><<<gP, blk, SMEM_TOTAL>>>(xhi, wkhi, DIM, DIM, BATCH, 1.f,
                                         nullptr, khi, nullptr, nullptr);
    gemm_mma<5><<<gP, blk, SMEM_TOTAL>>>(xhi, wvhi, DIM, DIM, BATCH, 1.f,
                                         nullptr, vthi, nullptr, nullptr);

    // probs = exp((k @ q^T)/32) bf16 + per-CTA row partial sums
    gemm_mma<6><<<gS, blk, SMEM_TOTAL>>>(khi, qhi, DIM, BATCH, BATCH, 0.03125f,
                                         psum, phi, nullptr, nullptr);

    // reciprocal row sums
    rowsum_recip<<<BATCH / 256, 256>>>(psum, rsum);

    // av = (P @ v) * rsum[row]  (B = v^T, K = 4096, bf16 out)
    gemm_mma<7><<<gP, blk, SMEM_TOTAL>>>(phi, vthi, BATCH, DIM, BATCH, 1.f,
                                         nullptr, avhi, rsum, nullptr);

    // h = av @ fcw^T + fcb + x  (fp32 out)
    gemm_mma<3><<<gP, blk, SMEM_TOTAL>>>(avhi, fwhi, DIM, DIM, BATCH, 1.f,
                                         h, nullptr, fcb, x);

    // layernorm -> out
    layernorm_rows<<<BATCH, 256>>>(h, gamma, beta, out);
}

// round 11
// speedup vs baseline: 1.1215x; 1.1215x over previous
#include <cuda_runtime.h>
#include <cuda_bf16.h>
#include <math.h>
#include <stdint.h>

#define BATCH 4096
#define DIM   1024
#define LN_EPS 1e-5f

// ---------------- GEMM tiling (R8 champion config) ----------------
#define BM 128
#define BN 128
#define BK 64
#define NSTG 2
#define ROW_HALFS 72                    // 64 data + 8 pad halves (144 B row stride)
#define A_BYTES (BM * ROW_HALFS * 2)    // 18432
#define B_BYTES (BN * ROW_HALFS * 2)    // 18432
#define STG_BYTES (A_BYTES + B_BYTES)   // 36864
#define SMEM_TOTAL (NSTG * STG_BYTES)   // 73728  (2 CTAs/SM -> 147 KB)

// ---------------- scratch (static device globals) ----------------
__device__ __align__(256) __nv_bfloat16 g_xhi [(size_t)BATCH * DIM];
__device__ __align__(256) __nv_bfloat16 g_wqhi[(size_t)DIM * DIM];
__device__ __align__(256) __nv_bfloat16 g_wkhi[(size_t)DIM * DIM];
__device__ __align__(256) __nv_bfloat16 g_wvhi[(size_t)DIM * DIM];
__device__ __align__(256) __nv_bfloat16 g_fwhi[(size_t)DIM * DIM];
__device__ __align__(256) __nv_bfloat16 g_qhi [(size_t)BATCH * DIM];
__device__ __align__(256) __nv_bfloat16 g_khi [(size_t)BATCH * DIM];
__device__ __align__(256) __nv_bfloat16 g_vthi[(size_t)DIM * BATCH];    // V^T [DIM, BATCH]
__device__ __align__(256) __nv_bfloat16 g_phi [(size_t)BATCH * BATCH];  // exp-probs bf16 (unnormalized)
__device__ __align__(256) float         g_psum[(size_t)32 * BATCH];     // per-colblock row partial sums
__device__ __align__(256) float         g_rsum[(size_t)BATCH];          // reciprocal row sums
__device__ __align__(256) __nv_bfloat16 g_avhi[(size_t)BATCH * DIM];
__device__ __align__(256) float         g_h   [(size_t)BATCH * DIM];

// ---------------- PTX helpers ----------------
__device__ __forceinline__ uint32_t smem_u32(const void* p) {
    uint32_t a;
    asm("{ .reg .u64 t; cvta.to.shared.u64 t, %1; cvt.u32.u64 %0, t; }" : "=r"(a) : "l"(p));
    return a;
}

#define CP_ASYNC16(dst, src) \
    asm volatile("cp.async.cg.shared.global [%0], [%1], 16;" :: "r"(dst), "l"(src) : "memory")
#define CP_COMMIT() asm volatile("cp.async.commit_group;" ::: "memory")
#define CP_WAIT()   asm volatile("cp.async.wait_group %0;" :: "n"(NSTG - 2) : "memory")
#define CP_WAIT0()  asm volatile("cp.async.wait_group 0;" ::: "memory")

__device__ __forceinline__ void ldm4(uint32_t& r0, uint32_t& r1, uint32_t& r2, uint32_t& r3,
                                     uint32_t addr) {
    asm volatile("ldmatrix.sync.aligned.m8n8.x4.shared.b16 {%0,%1,%2,%3}, [%4];"
                 : "=r"(r0), "=r"(r1), "=r"(r2), "=r"(r3) : "r"(addr));
}

__device__ __forceinline__ void mma16816(float& c0, float& c1, float& c2, float& c3,
                                         uint32_t a0, uint32_t a1, uint32_t a2, uint32_t a3,
                                         uint32_t b0, uint32_t b1) {
    asm volatile("mma.sync.aligned.m16n8k16.row.col.f32.bf16.bf16.f32 "
                 "{%0,%1,%2,%3}, {%4,%5,%6,%7}, {%8,%9}, {%0,%1,%2,%3};"
                 : "+f"(c0), "+f"(c1), "+f"(c2), "+f"(c3)
                 : "r"(a0), "r"(a1), "r"(a2), "r"(a3), "r"(b0), "r"(b1));
}

// stage loader: A tile 128x64 bf16 + B tile 128x64 bf16, padded rows (144B stride)
__device__ __forceinline__ void load_stage(
    uint32_t sbase, int tid,
    const __nv_bfloat16* __restrict__ A, const __nv_bfloat16* __restrict__ B, int K)
{
    #pragma unroll
    for (int i = 0; i < 8; i++) {
        int c   = tid + i * 256;          // 0..2047 chunk id (16B chunks)
        int cc  = c & 1023;
        int row = cc >> 3;                // 0..127
        int col = cc & 7;                 // 0..7
        const __nv_bfloat16* src = (c < 1024 ? A : B) + (size_t)row * K + col * 8;
        uint32_t dst = sbase + (c < 1024 ? 0 : A_BYTES) + row * (ROW_HALFS * 2) + col * 16;
        CP_ASYNC16(dst, src);
    }
}

// ---------------- shared GEMM core: acc += A_tile x B_tile^T over K ---------
__device__ __forceinline__ void gemm_core(
    float acc[4][4][4],
    const __nv_bfloat16* __restrict__ A, const __nv_bfloat16* __restrict__ B,
    int K, uint32_t sb, int tid, int warp_m, int warp_n, int lid,
    size_t arow, size_t brow)
{
    const int T = K / BK;

    const int a_r  = lid & 15;
    const int a_k8 = (lid >> 4) & 1;
    const int b_r  = lid & 7;
    const int b_t  = (lid >> 4) & 1;
    const int b_k8 = (lid >> 3) & 1;

    #pragma unroll
    for (int u = 0; u < NSTG - 1; u++) {
        load_stage(sb + u * STG_BYTES, tid, A + arow + u * BK, B + brow + u * BK, K);
        CP_COMMIT();
    }

    for (int t = 0; t < T; t++) {
        CP_WAIT();
        __syncthreads();

        const int u = t + NSTG - 1;
        if (u < T) {
            int su = u & (NSTG - 1);
            load_stage(sb + su * STG_BYTES, tid, A + arow + u * BK, B + brow + u * BK, K);
        }
        CP_COMMIT();

        const uint32_t aB = sb + (t & (NSTG - 1)) * STG_BYTES;
        const uint32_t bB = aB + A_BYTES;
        #pragma unroll
        for (int ks = 0; ks < 4; ks++) {
            uint32_t a[4][4];
            #pragma unroll
            for (int mi = 0; mi < 4; mi++) {
                uint32_t addr = aB +
                    ((warp_m * 64 + mi * 16 + a_r) * ROW_HALFS + ks * 16 + a_k8 * 8) * 2;
                ldm4(a[mi][0], a[mi][1], a[mi][2], a[mi][3], addr);
            }
            uint32_t b[4][2];
            #pragma unroll
            for (int j = 0; j < 2; j++) {
                uint32_t addr = bB +
                    ((warp_n * 32 + (2 * j + b_t) * 8 + b_r) * ROW_HALFS + ks * 16 + b_k8 * 8) * 2;
                ldm4(b[2 * j][0], b[2 * j][1], b[2 * j + 1][0], b[2 * j + 1][1], addr);
            }
            #pragma unroll
            for (int mi = 0; mi < 4; mi++)
                #pragma unroll
                for (int ni = 0; ni < 4; ni++)
                    mma16816(acc[mi][ni][0], acc[mi][ni][1], acc[mi][ni][2], acc[mi][ni][3],
                             a[mi][0], a[mi][1], a[mi][2], a[mi][3],
                             b[ni][0], b[ni][1]);
        }
    }
}

// ---------------- fused QKV projection: z selects (W, out, transpose) -------
__global__ __launch_bounds__(256, 2) void gemm_qkv(
    const __nv_bfloat16* __restrict__ X,
    const __nv_bfloat16* __restrict__ Wq, const __nv_bfloat16* __restrict__ Wk,
    const __nv_bfloat16* __restrict__ Wv,
    __nv_bfloat16* __restrict__ Q, __nv_bfloat16* __restrict__ Ko,
    __nv_bfloat16* __restrict__ Vt)
{
    extern __shared__ __align__(16) char smem_raw[];
    const uint32_t sb = smem_u32(smem_raw);
    const int tid = threadIdx.x;
    const int wid = tid >> 5;
    const int lid = tid & 31;
    const int warp_m = wid >> 2;
    const int warp_n = wid & 3;
    const int z = blockIdx.z;

    const __nv_bfloat16* W = (z == 0) ? Wq : (z == 1) ? Wk : Wv;

    float acc[4][4][4];
    #pragma unroll
    for (int i = 0; i < 4; i++)
        #pragma unroll
        for (int j = 0; j < 4; j++)
            #pragma unroll
            for (int e = 0; e < 4; e++) acc[i][j][e] = 0.f;

    gemm_core(acc, X, W, DIM, sb, tid, warp_m, warp_n, lid,
              (size_t)blockIdx.y * BM * DIM, (size_t)blockIdx.x * BN * DIM);

    const int qr = lid >> 2;
    const int qc = (lid & 3) * 2;
    #pragma unroll
    for (int mi = 0; mi < 4; mi++) {
        #pragma unroll
        for (int half = 0; half < 2; half++) {
            const int r = blockIdx.y * BM + warp_m * 64 + mi * 16 + qr + half * 8;
            #pragma unroll
            for (int ni = 0; ni < 4; ni++) {
                const int c = blockIdx.x * BN + warp_n * 32 + ni * 8 + qc;
                float f0 = acc[mi][ni][half * 2 + 0];
                float f1 = acc[mi][ni][half * 2 + 1];
                if (z == 0) {
                    *reinterpret_cast<__nv_bfloat162*>(Q + (size_t)r * DIM + c) =
                        __halves2bfloat162(__float2bfloat16_rn(f0), __float2bfloat16_rn(f1));
                } else if (z == 1) {
                    *reinterpret_cast<__nv_bfloat162*>(Ko + (size_t)r * DIM + c) =
                        __halves2bfloat162(__float2bfloat16_rn(f0), __float2bfloat16_rn(f1));
                } else {  // V transposed
                    Vt[(size_t)(c + 0) * BATCH + r] = __float2bfloat16_rn(f0);
                    Vt[(size_t)(c + 1) * BATCH + r] = __float2bfloat16_rn(f1);
                }
            }
        }
    }
}

// ---------------- HMMA GEMM (epilogue modes) ----------------
// MODE 3: Cf = acc + bias[col] + resid
// MODE 6: Chi = bf16(exp(alpha*acc)); Cf = per-CTA row partial sums
// MODE 7: Chi = bf16(acc * bias[row])
template<int MODE>
__global__ __launch_bounds__(256, 2) void gemm_mma(
    const __nv_bfloat16* __restrict__ Ahi,
    const __nv_bfloat16* __restrict__ Bhi,
    int K, int N, int Mtot, float alpha,
    float* __restrict__ Cf, __nv_bfloat16* __restrict__ Chi,
    const float* __restrict__ bias, const float* __restrict__ resid)
{
    extern __shared__ __align__(16) char smem_raw[];
    const uint32_t sb = smem_u32(smem_raw);
    const int tid = threadIdx.x;
    const int wid = tid >> 5;
    const int lid = tid & 31;
    const int warp_m = wid >> 2;
    const int warp_n = wid & 3;

    float acc[4][4][4];
    #pragma unroll
    for (int i = 0; i < 4; i++)
        #pragma unroll
        for (int j = 0; j < 4; j++)
            #pragma unroll
            for (int e = 0; e < 4; e++) acc[i][j][e] = 0.f;

    gemm_core(acc, Ahi, Bhi, K, sb, tid, warp_m, warp_n, lid,
              (size_t)blockIdx.y * BM * K, (size_t)blockIdx.x * BN * K);

    const int qr = lid >> 2;
    const int qc = (lid & 3) * 2;

    if (MODE == 6) {
        CP_WAIT0();
        __syncthreads();
        float* ps = reinterpret_cast<float*>(smem_raw);   // [4][128]
        #pragma unroll
        for (int mi = 0; mi < 4; mi++) {
            #pragma unroll
            for (int half = 0; half < 2; half++) {
                const int rl = warp_m * 64 + mi * 16 + qr + half * 8;
                const int r  = blockIdx.y * BM + rl;
                float rp = 0.f;
                #pragma unroll
                for (int ni = 0; ni < 4; ni++) {
                    const int c = blockIdx.x * BN + warp_n * 32 + ni * 8 + qc;
                    float p0 = __expf(acc[mi][ni][half * 2 + 0] * alpha);
                    float p1 = __expf(acc[mi][ni][half * 2 + 1] * alpha);
                    *reinterpret_cast<__nv_bfloat162*>(Chi + (size_t)r * N + c) =
                        __halves2bfloat162(__float2bfloat16_rn(p0), __float2bfloat16_rn(p1));
                    rp += p0 + p1;
                }
                rp += __shfl_xor_sync(0xffffffffu, rp, 1);
                rp += __shfl_xor_sync(0xffffffffu, rp, 2);
                if ((lid & 3) == 0) ps[warp_n * 128 + rl] = rp;
            }
        }
        __syncthreads();
        if (tid < 128) {
            float s = ps[tid] + ps[128 + tid] + ps[256 + tid] + ps[384 + tid];
            Cf[(size_t)blockIdx.x * Mtot + blockIdx.y * BM + tid] = s;
        }
        return;
    }

    #pragma unroll
    for (int mi = 0; mi < 4; mi++) {
        #pragma unroll
        for (int half = 0; half < 2; half++) {
            const int r = blockIdx.y * BM + warp_m * 64 + mi * 16 + qr + half * 8;
            const float rs = (MODE == 7) ? bias[r] : 0.f;
            #pragma unroll
            for (int ni = 0; ni < 4; ni++) {
                const int c = blockIdx.x * BN + warp_n * 32 + ni * 8 + qc;
                float f0 = acc[mi][ni][half * 2 + 0];
                float f1 = acc[mi][ni][half * 2 + 1];
                if (MODE == 3) {
                    const float2 b2 = *reinterpret_cast<const float2*>(bias + c);
                    const float2 x2 = *reinterpret_cast<const float2*>(resid + (size_t)r * N + c);
                    float2 o = {f0 + b2.x + x2.x, f1 + b2.y + x2.y};
                    *reinterpret_cast<float2*>(Cf + (size_t)r * N + c) = o;
                } else { // MODE 7
                    *reinterpret_cast<__nv_bfloat162*>(Chi + (size_t)r * N + c) =
                        __halves2bfloat162(__float2bfloat16_rn(f0 * rs),
                                           __float2bfloat16_rn(f1 * rs));
                }
            }
        }
    }
}

// ---------------- reciprocal row sums ----------------
__global__ __launch_bounds__(256) void rowsum_recip(
    const float* __restrict__ ps, float* __restrict__ rs)
{
    int r = blockIdx.x * 256 + threadIdx.x;
    float s = 0.f;
    #pragma unroll
    for (int b = 0; b < 32; b++) s += ps[(size_t)b * BATCH + r];
    rs[r] = 1.f / s;
}

// ---------------- fp32 -> bf16 convert (5 tensors, one launch) --------------
__global__ __launch_bounds__(256) void cvt_bf16_all(
    const float* __restrict__ s0, const float* __restrict__ s1,
    const float* __restrict__ s2, const float* __restrict__ s3,
    const float* __restrict__ s4,
    __nv_bfloat16* __restrict__ d0, __nv_bfloat16* __restrict__ d1,
    __nv_bfloat16* __restrict__ d2, __nv_bfloat16* __restrict__ d3,
    __nv_bfloat16* __restrict__ d4,
    int nW4, int nX4)
{
    const int y = blockIdx.y;
    const float* src = y == 0 ? s0 : y == 1 ? s1 : y == 2 ? s2 : y == 3 ? s3 : s4;
    __nv_bfloat16* dst = y == 0 ? d0 : y == 1 ? d1 : y == 2 ? d2 : y == 3 ? d3 : d4;
    const int n4 = (y == 4) ? nX4 : nW4;
    int i = blockIdx.x * 256 + threadIdx.x;
    if (i >= n4) return;
    float4 v = reinterpret_cast<const float4*>(src)[i];
    reinterpret_cast<__nv_bfloat162*>(dst)[i * 2 + 0] =
        __halves2bfloat162(__float2bfloat16_rn(v.x), __float2bfloat16_rn(v.y));
    reinterpret_cast<__nv_bfloat162*>(dst)[i * 2 + 1] =
        __halves2bfloat162(__float2bfloat16_rn(v.z), __float2bfloat16_rn(v.w));
}

// ---------------- layernorm ----------------
__global__ __launch_bounds__(256) void layernorm_rows(
    const float* __restrict__ H, const float* __restrict__ gamma,
    const float* __restrict__ beta, float* __restrict__ out)
{
    __shared__ float redS[8], redQ[8];
    const int tid = threadIdx.x;
    const float* p = H + (size_t)blockIdx.x * DIM;

    float4 v = *reinterpret_cast<const float4*>(p + tid * 4);
    float s  = v.x + v.y + v.z + v.w;
    float ss = v.x * v.x + v.y * v.y + v.z * v.z + v.w * v.w;
    #pragma unroll
    for (int o = 16; o; o >>= 1) {
        s  += __shfl_xor_sync(0xffffffffu, s, o);
        ss += __shfl_xor_sync(0xffffffffu, ss, o);
    }
    if ((tid & 31) == 0) { redS[tid >> 5] = s; redQ[tid >> 5] = ss; }
    __syncthreads();
    s = 0.f; ss = 0.f;
    #pragma unroll
    for (int i = 0; i < 8; i++) { s += redS[i]; ss += redQ[i]; }

    const float mu  = s * (1.f / DIM);
    const float var = ss * (1.f / DIM) - mu * mu;
    const float rs  = rsqrtf(var + LN_EPS);

    float4 g = *reinterpret_cast<const float4*>(gamma + tid * 4);
    float4 b = *reinterpret_cast<const float4*>(beta  + tid * 4);
    float4 o;
    o.x = (v.x - mu) * rs * g.x + b.x;
    o.y = (v.y - mu) * rs * g.y + b.y;
    o.z = (v.z - mu) * rs * g.z + b.z;
    o.w = (v.w - mu) * rs * g.w + b.w;
    *reinterpret_cast<float4*>(out + (size_t)blockIdx.x * DIM + tid * 4) = o;
}

// ---------------- launch ----------------
extern "C" void kernel_launch(void* const* d_in, const int* in_sizes, int n_in,
                              void* d_out, int out_size)
{
    const float* x     = (const float*)d_in[0];
    const float* Wq    = (const float*)d_in[1];
    const float* Wk    = (const float*)d_in[2];
    const float* Wv    = (const float*)d_in[3];
    const float* fcw   = (const float*)d_in[4];
    const float* fcb   = (const float*)d_in[5];
    const float* gamma = (const float*)d_in[6];
    const float* beta  = (const float*)d_in[7];
    float* out = (float*)d_out;

    __nv_bfloat16 *xhi, *wqhi, *wkhi, *wvhi, *fwhi;
    __nv_bfloat16 *qhi, *khi, *vthi, *phi, *avhi;
    float *psum, *rsum, *h;
    cudaGetSymbolAddress((void**)&xhi,  g_xhi);
    cudaGetSymbolAddress((void**)&wqhi, g_wqhi);
    cudaGetSymbolAddress((void**)&wkhi, g_wkhi);
    cudaGetSymbolAddress((void**)&wvhi, g_wvhi);
    cudaGetSymbolAddress((void**)&fwhi, g_fwhi);
    cudaGetSymbolAddress((void**)&qhi,  g_qhi);
    cudaGetSymbolAddress((void**)&khi,  g_khi);
    cudaGetSymbolAddress((void**)&vthi, g_vthi);
    cudaGetSymbolAddress((void**)&phi,  g_phi);
    cudaGetSymbolAddress((void**)&psum, g_psum);
    cudaGetSymbolAddress((void**)&rsum, g_rsum);
    cudaGetSymbolAddress((void**)&avhi, g_avhi);
    cudaGetSymbolAddress((void**)&h,    g_h);

    cudaFuncSetAttribute(gemm_qkv,    cudaFuncAttributeMaxDynamicSharedMemorySize, SMEM_TOTAL);
    cudaFuncSetAttribute(gemm_mma<3>, cudaFuncAttributeMaxDynamicSharedMemorySize, SMEM_TOTAL);
    cudaFuncSetAttribute(gemm_mma<6>, cudaFuncAttributeMaxDynamicSharedMemorySize, SMEM_TOTAL);
    cudaFuncSetAttribute(gemm_mma<7>, cudaFuncAttributeMaxDynamicSharedMemorySize, SMEM_TOTAL);

    // convert all inputs to bf16 in one launch
    const int nX4 = BATCH * DIM / 4, nW4 = DIM * DIM / 4;
    cvt_bf16_all<<<dim3((nX4 + 255) / 256, 5), 256>>>(
        Wq, Wk, Wv, fcw, x, wqhi, wkhi, wvhi, fwhi, xhi, nW4, nX4);

    const dim3 blk(256);
    const dim3 gQKV(DIM / BN, BATCH / BM, 3);   // 8 x 32 x 3
    const dim3 gP(DIM / BN,   BATCH / BM);      // 8 x 32
    const dim3 gS(BATCH / BN, BATCH / BM);      // 32 x 32

    // fused q/k/v projections (v transposed)
    gemm_qkv<<<gQKV, blk, SMEM_TOTAL>>>(xhi, wqhi, wkhi, wvhi, qhi, khi, vthi);

    // probs = exp((k @ q^T)/32) bf16 + per-CTA row partial sums
    gemm_mma<6><<<gS, blk, SMEM_TOTAL>>>(khi, qhi, DIM, BATCH, BATCH, 0.03125f,
                                         psum, phi, nullptr, nullptr);

    // reciprocal row sums
    rowsum_recip<<<BATCH / 256, 256>>>(psum, rsum);

    // av = (P @ v) * rsum[row]
    gemm_mma<7><<<gP, blk, SMEM_TOTAL>>>(phi, vthi, BATCH, DIM, BATCH, 1.f,
                                         nullptr, avhi, rsum, nullptr);

    // h = av @ fcw^T + fcb + x
    gemm_mma<3><<<gP, blk, SMEM_TOTAL>>>(avhi, fwhi, DIM, DIM, BATCH, 1.f,
                                         h, nullptr, fcb, x);

    // layernorm -> out
    layernorm_rows<<<BATCH, 256>>>(h, gamma, beta, out);
}